// round 13
// baseline (speedup 1.0000x reference)
#include <cuda_runtime.h>
#include <cstdint>
#include <math.h>

// NetSimile on 8 block-diagonal graphs of 512 nodes, dense A[4096,4096] in {0,1}.
// TWO launches:
//   K1: bits (DRAM-bound, no smem) - stream order guarantees bits done for K2.
//   K2: feat -> f3 -> stats fused, per-graph atomic counters (self-resetting,
//       validated in R11). feat blocks never spin; f3/stats spin on resident
//       producers only.

#define NN 4096
#define GG 8
#define MM 512
#define WW 16   // 512 bits = 16 u32 words per row

#define B_FEAT 512
#define B_F3   512
#define B_STAT 7
#define NBLK2 (B_FEAT + B_F3 + B_STAT)

__device__ uint32_t g_bits[NN][WW];   // adjacency bitsets (no self bit)
__device__ int      g_deg[NN];
__device__ float    g_feat[7][NN];
// per-graph phase counters; zero-initialized, self-reset every run
__device__ int ctr_feat[GG];
__device__ int ctr_f3[GG];
__device__ int ctr_stat[GG];

__device__ __forceinline__ void spin_ge(volatile int* c, int target) {
    while (*c < target) __nanosleep(64);
}

// ---------------------------------------------------------------------------
// K1: build per-row bitsets + degree. One warp per row, MLP-16 loads.
// ---------------------------------------------------------------------------
__global__ void k_bits(const float* __restrict__ A) {
    int warp = (blockIdx.x * blockDim.x + threadIdx.x) >> 5;
    int lane = threadIdx.x & 31;
    if (warp >= NN) return;
    int g = warp / MM;
    const float* row = A + (size_t)warp * NN + (size_t)g * MM;

    float v[WW];
#pragma unroll
    for (int w = 0; w < WW; w++) v[w] = row[w * 32 + lane];

    uint32_t myword = 0;
    int deg = 0;
#pragma unroll
    for (int w = 0; w < WW; w++) {
        unsigned m = __ballot_sync(0xffffffffu, v[w] != 0.0f);
        deg += __popc(m);
        if (lane == w) myword = m;
    }
    if (lane < WW) g_bits[warp][lane] = myword;
    if (lane == 0) g_deg[warp] = deg;
}

// ---------------------------------------------------------------------------
// K2: feat -> f3 -> stats, phases by blockIdx range (deps point to lower bids).
// ---------------------------------------------------------------------------
__global__ void __launch_bounds__(256) k_rest(float* __restrict__ out) {
    __shared__ uint32_t sbits[MM][WW + 1];
    __shared__ int sdeg[MM];

    int bid = blockIdx.x;
    int tid = threadIdx.x, wid = tid >> 5, lane = tid & 31;
    const unsigned FULL = 0xffffffffu;

    // ============================ PHASE 1: feat ============================
    if (bid < B_FEAT) {
        int node0 = bid * 8;                  // 8 nodes/block, 64 blocks/graph
        int g = node0 >> 9, base = g << 9;
        // bits done: K1 completed before this kernel started (stream order)

        for (int idx = tid; idx < MM * WW; idx += 256) {
            int v = idx >> 4, w = idx & 15;
            sbits[v][w] = g_bits[base + v][w];
        }
        for (int idx = tid; idx < MM; idx += 256) sdeg[idx] = g_deg[base + idx];
        __syncthreads();

        int n = node0 + wid;
        int r = n - base;
        uint32_t m1[WW];
#pragma unroll
        for (int w = 0; w < WW; w++) m1[w] = sbits[r][w];
        m1[r >> 5] |= 1u << (r & 31);         // M1 = A | I

        int f4 = 0, sumdeg2 = 0, cnt2 = 0, sumdegn = 0;
        for (int v = lane; v < MM; v += 32) {
            int b = 0;
#pragma unroll
            for (int w = 0; w < WW; w++) b += __popc(m1[w] & sbits[v][w]);
            bool m1b = (m1[v >> 5] >> (v & 31)) & 1u;
            bool m2b = m1b || (b > 0);        // M2 = M1 | (B > 0)
            if (m1b) f4 += b;
            if (m2b) { cnt2++; sumdeg2 += sdeg[v]; }
            if (m1b && v != r) sumdegn += sdeg[v];
        }
        f4      = __reduce_add_sync(FULL, f4);
        sumdeg2 = __reduce_add_sync(FULL, sumdeg2);
        cnt2    = __reduce_add_sync(FULL, cnt2);
        sumdegn = __reduce_add_sync(FULL, sumdegn);

        if (lane == 0) {
            float deg = (float)sdeg[r];
            g_feat[0][n] = deg;
            g_feat[1][n] = (deg > 1.f) ? 2.0f * ((float)f4 - deg) / (deg * (deg - 1.0f)) : 0.f;
            g_feat[2][n] = (deg > 0.f) ? (float)sumdegn / deg : 0.f;
            g_feat[4][n] = 0.5f * (float)f4;
            g_feat[5][n] = (float)sumdeg2 - 2.0f * (float)f4;
            g_feat[6][n] = (float)cnt2 - deg - 1.0f;
        }
        __threadfence();
        __syncthreads();
        if (tid == 0) atomicAdd(&ctr_feat[g], 1);
        return;
    }

    // ============================ PHASE 2: f3 ==============================
    if (bid < B_FEAT + B_F3) {
        int fb = bid - B_FEAT;
        int n = fb * 8 + wid;                 // warp per node
        int g = n >> 9, base = g << 9;

        if (tid == 0) spin_ge(&ctr_feat[g], 64);
        __syncthreads();
        __threadfence();                      // acquire

        float s = 0.f;
#pragma unroll
        for (int k = 0; k < WW; k++) {
            uint32_t w = g_bits[n][k];
            if ((w >> lane) & 1u) s += g_feat[1][base + k * 32 + lane];
        }
#pragma unroll
        for (int o = 16; o; o >>= 1) s += __shfl_xor_sync(FULL, s, o);
        if (lane == 0) {
            float deg = (float)g_deg[n];
            g_feat[3][n] = (deg > 0.f) ? s / deg : 0.f;
        }
        __threadfence();
        __syncthreads();
        if (tid == 0) {
            int old = atomicAdd(&ctr_f3[g], 1);
            if (old == 63) ctr_feat[g] = 0;   // recycle for next replay
        }
        return;
    }

    // ============================ PHASE 3: stats ===========================
    {
        int sb = bid - (B_FEAT + B_F3);
        int id = sb * 8 + wid;                // 7 blocks x 8 warps = 56 warps
        int g = id / 7, f = id % 7;
        int base = g * MM;

        if (lane == 0) spin_ge(&ctr_f3[g], 64);
        __syncwarp();
        __threadfence();                      // acquire

        float xi[16];
#pragma unroll
        for (int j = 0; j < 16; j++) xi[j] = g_feat[f][base + lane + 32 * j];

        // ---- mean (fp32, pairwise) ----
        float pair8[8];
#pragma unroll
        for (int j = 0; j < 8; j++) pair8[j] = xi[2 * j] + xi[2 * j + 1];
        float q4a = (pair8[0] + pair8[1]) + (pair8[2] + pair8[3]);
        float q4b = (pair8[4] + pair8[5]) + (pair8[6] + pair8[7]);
        float sm = q4a + q4b;
#pragma unroll
        for (int o = 16; o; o >>= 1) sm += __shfl_xor_sync(FULL, sm, o);
        float mean = sm * (1.0f / (float)MM);

        // ---- median: 2-bit radix select with min/max early exit ----
        uint32_t keys[16];
#pragma unroll
        for (int j = 0; j < 16; j++) {
            uint32_t b = __float_as_uint(xi[j]);
            keys[j] = (b & 0x80000000u) ? ~b : (b ^ 0x80000000u);
        }
        uint32_t candm = 0xFFFFu;
        int k = (MM - 1) / 2;                 // 255
        uint32_t kv = 0;
        for (int bit = 30; bit >= 0; bit -= 2) {
            uint32_t mn = 0xFFFFFFFFu, mx = 0u, cnt = 0, bb = 0;
#pragma unroll
            for (int j = 0; j < 16; j++) {
                uint32_t kj = keys[j];
                uint32_t b = (kj >> bit) & 3u;
                bb |= b << (2 * j);
                if ((candm >> j) & 1u) {
                    mn = min(mn, kj);
                    mx = max(mx, kj);
                    cnt += (b < 3u) ? (1u << (10 * b)) : 0u;
                }
            }
            mn = __reduce_min_sync(FULL, mn);
            mx = __reduce_max_sync(FULL, mx);
            if (mn == mx) { kv = mn; break; }
            cnt = __reduce_add_sync(FULL, cnt);
            int c0 = cnt & 1023, c1 = (cnt >> 10) & 1023, c2 = (cnt >> 20) & 1023;
            uint32_t chosen;
            if (k < c0)                { chosen = 0u; }
            else if (k < c0 + c1)      { chosen = 1u; k -= c0; }
            else if (k < c0 + c1 + c2) { chosen = 2u; k -= c0 + c1; }
            else                       { chosen = 3u; k -= c0 + c1 + c2; }
            kv |= chosen << bit;
#pragma unroll
            for (int j = 0; j < 16; j++)
                if (((bb >> (2 * j)) & 3u) != chosen) candm &= ~(1u << j);
        }
        uint32_t mb = (kv & 0x80000000u) ? (kv ^ 0x80000000u) : ~kv;
        float medv = __uint_as_float(mb);

        // ---- central moments 2,3,4 (fp32, pairwise) ----
        float a2[8], a3[8], a4[8];
#pragma unroll
        for (int j = 0; j < 8; j++) {
            float c0 = xi[2 * j] - mean,  c1 = xi[2 * j + 1] - mean;
            float p0 = c0 * c0,           p1 = c1 * c1;
            a2[j] = p0 + p1;
            a3[j] = fmaf(p0, c0, p1 * c1);
            a4[j] = fmaf(p0, p0, p1 * p1);
        }
        float s2 = ((a2[0]+a2[1])+(a2[2]+a2[3])) + ((a2[4]+a2[5])+(a2[6]+a2[7]));
        float s3 = ((a3[0]+a3[1])+(a3[2]+a3[3])) + ((a3[4]+a3[5])+(a3[6]+a3[7]));
        float s4 = ((a4[0]+a4[1])+(a4[2]+a4[3])) + ((a4[4]+a4[5])+(a4[6]+a4[7]));
#pragma unroll
        for (int o = 16; o; o >>= 1) {
            s2 += __shfl_xor_sync(FULL, s2, o);
            s3 += __shfl_xor_sync(FULL, s3, o);
            s4 += __shfl_xor_sync(FULL, s4, o);
        }

        if (lane == 0) {
            float m2 = s2 * (1.0f / (float)MM);
            float m3 = s3 * (1.0f / (float)MM);
            float m4 = s4 * (1.0f / (float)MM);
            float eps = 1e-4f;
            float sq = sqrtf(m2);
            out[g * 35 + 0  + f] = mean;
            out[g * 35 + 7  + f] = medv;
            out[g * 35 + 14 + f] = sq;
            out[g * 35 + 21 + f] = m3 / fmaxf(m2 * sq, eps);
            out[g * 35 + 28 + f] = m4 / fmaxf(m2 * m2, eps);
            // recycle counters for next replay (last stats warp of graph g)
            __threadfence();
            int old = atomicAdd(&ctr_stat[g], 1);
            if (old == 6) { ctr_f3[g] = 0; ctr_stat[g] = 0; }
        }
    }
}

extern "C" void kernel_launch(void* const* d_in, const int* in_sizes, int n_in,
                              void* d_out, int out_size) {
    const float* A = (const float*)d_in[0];
    float* out = (float*)d_out;
    k_bits<<<NN / 8, 256>>>(A);
    k_rest<<<NBLK2, 256>>>(out);
}

// round 14
// speedup vs baseline: 1.5726x; 1.5726x over previous
#include <cuda_runtime.h>
#include <cstdint>
#include <math.h>

// NetSimile on 8 block-diagonal graphs of 512 nodes, dense A[4096,4096] in {0,1}.
// 4 launches (R10 structure). This round: k_feat switched from dense v-loop
// (256 LDS/thread) to sparse ego1-row loop over the staged smem tile
// (~17 rows/node), using adjacency symmetry: (B>0)-mask == OR of ego1 rows.

#define NN 4096
#define GG 8
#define MM 512
#define WW 16    // 512 bits = 16 u32 words per row
#define LMAX 64  // ego1 list capacity (deg+1, max deg ~35 whp)

__device__ uint32_t g_bits[NN][WW];   // adjacency bitsets (no self bit)
__device__ int      g_deg[NN];
__device__ float    g_feat[7][NN];

// ---------------------------------------------------------------------------
// K1: build per-row bitsets + degree. One warp per row, MLP-16 loads.
// ---------------------------------------------------------------------------
__global__ void k_bits(const float* __restrict__ A) {
    int warp = (blockIdx.x * blockDim.x + threadIdx.x) >> 5;
    int lane = threadIdx.x & 31;
    if (warp >= NN) return;
    int g = warp / MM;
    const float* row = A + (size_t)warp * NN + (size_t)g * MM;

    float v[WW];
#pragma unroll
    for (int w = 0; w < WW; w++) v[w] = row[w * 32 + lane];

    uint32_t myword = 0;
    int deg = 0;
#pragma unroll
    for (int w = 0; w < WW; w++) {
        unsigned m = __ballot_sync(0xffffffffu, v[w] != 0.0f);
        deg += __popc(m);
        if (lane == w) myword = m;
    }
    if (lane < WW) g_bits[warp][lane] = myword;
    if (lane == 0) g_deg[warp] = deg;
}

// ---------------------------------------------------------------------------
// K2: per-node features f0,f1,f2,f4,f5,f6. One warp per node, 8 warps/block.
// Tile staged in smem (17-word pitch, conflict-free), then SPARSE inner loop:
//   f4      = sum_{v in ego1} popc(m1 & adj(v))   (~17 rows, not 512)
//   m2      = m1 | OR_{v in ego1} adj(v)          (symmetry: b>0 <=> in OR)
//   sums over m2 / adj bits via 16 lane-parallel predicated LDS iterations.
// ---------------------------------------------------------------------------
__global__ void __launch_bounds__(256) k_feat() {
    __shared__ uint32_t sbits[MM][WW + 1];
    __shared__ int sdeg[MM];
    __shared__ uint16_t slist[8][LMAX];
    int tid = threadIdx.x;
    int wid = tid >> 5, lane = tid & 31;
    const unsigned FULL = 0xffffffffu;
    int node0 = blockIdx.x * 8;
    int g = node0 >> 9, base = g << 9;

    for (int idx = tid; idx < MM * WW; idx += 256) {
        int v = idx >> 4, w = idx & 15;
        sbits[v][w] = g_bits[base + v][w];
    }
    for (int idx = tid; idx < MM; idx += 256) sdeg[idx] = g_deg[base + idx];
    __syncthreads();

    int n = node0 + wid;
    int r = n - base;

    // m1 row: lane<16 holds word 'lane' (adj | self), broadcast to registers.
    uint32_t w0 = (lane < WW) ? sbits[r][lane] : 0u;
    if (lane == (r >> 5)) w0 |= 1u << (r & 31);
    uint32_t m1w[WW];
#pragma unroll
    for (int w = 0; w < WW; w++) m1w[w] = __shfl_sync(FULL, w0, w);

    // compact ego1 list (validated logic): exclusive prefix of word popcounts
    int pc = (lane < WW) ? __popc(w0) : 0;
    int off = pc;
#pragma unroll
    for (int o = 1; o < 32; o <<= 1) {
        int v = __shfl_up_sync(FULL, off, o);
        if (lane >= o) off += v;
    }
    int total = __shfl_sync(FULL, off, 31);   // = deg + 1
    if (total > LMAX) total = LMAX;
    off -= pc;
    uint32_t wrem = w0;
    while (wrem) {
        int b = __ffs(wrem) - 1;
        wrem &= wrem - 1;
        if (off < LMAX) slist[wid][off] = (uint16_t)(lane * 32 + b);
        off++;
    }
    __syncwarp();

    // sparse main loop: ~17 rows from the staged tile
    int f4 = 0, sumdegn = 0;
    uint32_t or16[WW];
#pragma unroll
    for (int w = 0; w < WW; w++) or16[w] = 0u;

    for (int i = lane; i < total; i += 32) {
        int v = slist[wid][i];
        int p = 0;
#pragma unroll
        for (int w = 0; w < WW; w++) {
            uint32_t aw = sbits[v][w];
            p += __popc(m1w[w] & aw);
            or16[w] |= aw;
        }
        f4 += p;
        if (v != r) sumdegn += sdeg[v];
    }
    f4      = __reduce_add_sync(FULL, f4);
    sumdegn = __reduce_add_sync(FULL, sumdegn);

    // m2 words in every lane's registers; cnt2 identical on all lanes
    int cnt2 = 0;
#pragma unroll
    for (int w = 0; w < WW; w++) {
        or16[w] = __reduce_or_sync(FULL, or16[w]) | m1w[w];
        cnt2 += __popc(or16[w]);
    }

    // sumdeg2 = sum of deg over m2 bits: lane-parallel, conflict-free LDS
    int sumdeg2 = 0;
#pragma unroll
    for (int i = 0; i < WW; i++) {
        if ((or16[i] >> lane) & 1u) sumdeg2 += sdeg[i * 32 + lane];
    }
    sumdeg2 = __reduce_add_sync(FULL, sumdeg2);

    if (lane == 0) {
        float deg = (float)sdeg[r];
        g_feat[0][n] = deg;
        g_feat[1][n] = (deg > 1.f) ? 2.0f * ((float)f4 - deg) / (deg * (deg - 1.0f)) : 0.f;
        g_feat[2][n] = (deg > 0.f) ? (float)sumdegn / deg : 0.f;
        g_feat[4][n] = 0.5f * (float)f4;
        g_feat[5][n] = (float)sumdeg2 - 2.0f * (float)f4;
        g_feat[6][n] = (float)cnt2 - deg - 1.0f;
    }
}

// ---------------------------------------------------------------------------
// K3: f3 = scatter_mean of neighbor f1. One warp per node.
// ---------------------------------------------------------------------------
__global__ void k_f3() {
    int warp = (blockIdx.x * blockDim.x + threadIdx.x) >> 5;
    int lane = threadIdx.x & 31;
    if (warp >= NN) return;
    int g = warp / MM;
    int base = g * MM;
    float s = 0.f;
#pragma unroll
    for (int k = 0; k < WW; k++) {
        uint32_t w = g_bits[warp][k];
        if ((w >> lane) & 1u) s += g_feat[1][base + k * 32 + lane];
    }
#pragma unroll
    for (int o = 16; o; o >>= 1) s += __shfl_xor_sync(0xffffffffu, s, o);
    if (lane == 0) {
        float deg = (float)g_deg[warp];
        g_feat[3][warp] = (deg > 0.f) ? s / deg : 0.f;
    }
}

// ---------------------------------------------------------------------------
// K4: per (graph, feature) stats. ONE WARP per (g,f), all-fp32 (R10 version).
// ---------------------------------------------------------------------------
__global__ void __launch_bounds__(32) k_stats(float* __restrict__ out) {
    int id = blockIdx.x;          // 0..55
    int g = id / 7, f = id % 7;
    int lane = threadIdx.x;
    int base = g * MM;
    const unsigned FULL = 0xffffffffu;

    float xi[16];
#pragma unroll
    for (int j = 0; j < 16; j++) xi[j] = g_feat[f][base + lane + 32 * j];

    // ---- mean (fp32, pairwise) ----
    float pair8[8];
#pragma unroll
    for (int j = 0; j < 8; j++) pair8[j] = xi[2 * j] + xi[2 * j + 1];
    float q4a = (pair8[0] + pair8[1]) + (pair8[2] + pair8[3]);
    float q4b = (pair8[4] + pair8[5]) + (pair8[6] + pair8[7]);
    float sm = q4a + q4b;
#pragma unroll
    for (int o = 16; o; o >>= 1) sm += __shfl_xor_sync(FULL, sm, o);
    float mean = sm * (1.0f / (float)MM);

    // ---- median: 2-bit radix select with min/max early exit ----
    uint32_t keys[16];
#pragma unroll
    for (int j = 0; j < 16; j++) {
        uint32_t b = __float_as_uint(xi[j]);
        keys[j] = (b & 0x80000000u) ? ~b : (b ^ 0x80000000u);
    }
    uint32_t candm = 0xFFFFu;
    int k = (MM - 1) / 2;   // 255
    uint32_t kv = 0;
    for (int bit = 30; bit >= 0; bit -= 2) {
        uint32_t mn = 0xFFFFFFFFu, mx = 0u, cnt = 0, bb = 0;
#pragma unroll
        for (int j = 0; j < 16; j++) {
            uint32_t kj = keys[j];
            uint32_t b = (kj >> bit) & 3u;
            bb |= b << (2 * j);
            if ((candm >> j) & 1u) {
                mn = min(mn, kj);
                mx = max(mx, kj);
                cnt += (b < 3u) ? (1u << (10 * b)) : 0u;
            }
        }
        mn = __reduce_min_sync(FULL, mn);
        mx = __reduce_max_sync(FULL, mx);
        if (mn == mx) { kv = mn; break; }
        cnt = __reduce_add_sync(FULL, cnt);
        int c0 = cnt & 1023, c1 = (cnt >> 10) & 1023, c2 = (cnt >> 20) & 1023;
        uint32_t chosen;
        if (k < c0)                { chosen = 0u; }
        else if (k < c0 + c1)      { chosen = 1u; k -= c0; }
        else if (k < c0 + c1 + c2) { chosen = 2u; k -= c0 + c1; }
        else                       { chosen = 3u; k -= c0 + c1 + c2; }
        kv |= chosen << bit;
#pragma unroll
        for (int j = 0; j < 16; j++)
            if (((bb >> (2 * j)) & 3u) != chosen) candm &= ~(1u << j);
    }
    uint32_t mb = (kv & 0x80000000u) ? (kv ^ 0x80000000u) : ~kv;
    float medv = __uint_as_float(mb);

    // ---- central moments 2,3,4 (fp32, pairwise) ----
    float a2[8], a3[8], a4[8];
#pragma unroll
    for (int j = 0; j < 8; j++) {
        float c0 = xi[2 * j] - mean,  c1 = xi[2 * j + 1] - mean;
        float p0 = c0 * c0,           p1 = c1 * c1;
        a2[j] = p0 + p1;
        a3[j] = fmaf(p0, c0, p1 * c1);
        a4[j] = fmaf(p0, p0, p1 * p1);
    }
    float s2 = ((a2[0]+a2[1])+(a2[2]+a2[3])) + ((a2[4]+a2[5])+(a2[6]+a2[7]));
    float s3 = ((a3[0]+a3[1])+(a3[2]+a3[3])) + ((a3[4]+a3[5])+(a3[6]+a3[7]));
    float s4 = ((a4[0]+a4[1])+(a4[2]+a4[3])) + ((a4[4]+a4[5])+(a4[6]+a4[7]));
#pragma unroll
    for (int o = 16; o; o >>= 1) {
        s2 += __shfl_xor_sync(FULL, s2, o);
        s3 += __shfl_xor_sync(FULL, s3, o);
        s4 += __shfl_xor_sync(FULL, s4, o);
    }

    if (lane == 0) {
        float m2 = s2 * (1.0f / (float)MM);
        float m3 = s3 * (1.0f / (float)MM);
        float m4 = s4 * (1.0f / (float)MM);
        float eps = 1e-4f;
        float sq = sqrtf(m2);
        out[g * 35 + 0  + f] = mean;
        out[g * 35 + 7  + f] = medv;
        out[g * 35 + 14 + f] = sq;
        out[g * 35 + 21 + f] = m3 / fmaxf(m2 * sq, eps);
        out[g * 35 + 28 + f] = m4 / fmaxf(m2 * m2, eps);
    }
}

extern "C" void kernel_launch(void* const* d_in, const int* in_sizes, int n_in,
                              void* d_out, int out_size) {
    const float* A = (const float*)d_in[0];
    float* out = (float*)d_out;

    k_bits<<<NN / 8, 256>>>(A);      // bitsets + degree (MLP-16 loads)
    k_feat<<<NN / 8, 256>>>();       // SPARSE ego1-row feature pass
    k_f3<<<NN / 8, 256>>>();         // neighbor-mean of f1
    k_stats<<<GG * 7, 32>>>(out);    // warp per (graph, feature), all-fp32
}